// round 11
// baseline (speedup 1.0000x reference)
#include <cuda_runtime.h>
#include <math.h>

// UserCollaborativeFiltering — round 11.
// R10 proved the (t,i)-sort cuts gather traffic (175->140MB, main kernel
// 34.7->28.1us) but its 3-kernel pipeline cost ~7.5us and ate the win.
// This round fuses hist+scan+scatter into ONE single-block kernel using
// shared memory only (~3us), and sharpens the key to (t, i>>5) so exact
// 64B-line sharers are strictly warp-adjacent.

#define JMAX 5            // ceil(142/32)
#define NBINS_PAD 9216    // 1024 threads * 9 bins each
#define BINS_PER_THREAD 9
#define PERM_CAP (1<<20)

__device__ int g_perm[PERM_CAP];

// Monotone float -> u32 (order-preserving). 0u reserved as "removed".
__device__ __forceinline__ unsigned f2ord(float f) {
    unsigned b = __float_as_uint(f);
    return (b & 0x80000000u) ? ~b : (b | 0x80000000u);
}
__device__ __forceinline__ float ord2f(unsigned o) {
    unsigned b = (o & 0x80000000u) ? (o ^ 0x80000000u) : ~o;
    return __uint_as_float(b);
}

// ---- fused single-block counting sort (hist -> scan -> scatter) ----------
// key = t * ceil(I/32) + (i>>5). Requires T*ceil(I/32) <= NBINS_PAD.

__global__ void __launch_bounds__(1024) k_sort(
    const int* __restrict__ time_id, const int* __restrict__ item_id,
    int B, int bpt /* bins per t = ceil(I/32) */)
{
    __shared__ int hist[NBINS_PAD];  // 36KB
    const int tid = threadIdx.x;

    #pragma unroll
    for (int j = 0; j < BINS_PER_THREAD; j++) hist[tid + j * 1024] = 0;
    __syncthreads();

    // Phase A: histogram (shared atomics, ~2-deep average).
    for (int i = tid; i < B; i += 1024)
        atomicAdd(&hist[time_id[i] * bpt + (item_id[i] >> 5)], 1);
    __syncthreads();

    // Phase B: exclusive scan over NBINS_PAD bins.
    // Each thread owns 9 consecutive bins [tid*9, tid*9+9).
    const int base_bin = tid * BINS_PER_THREAD;
    int v[BINS_PER_THREAD];
    int tsum = 0;
    #pragma unroll
    for (int j = 0; j < BINS_PER_THREAD; j++) {
        v[j] = hist[base_bin + j];
        tsum += v[j];
    }
    // warp inclusive scan of thread totals
    const int lane = tid & 31, wid = tid >> 5;
    int inc = tsum;
    #pragma unroll
    for (int off = 1; off < 32; off <<= 1) {
        int n = __shfl_up_sync(0xffffffffu, inc, off);
        if (lane >= off) inc += n;
    }
    __shared__ int wsum[32];
    if (lane == 31) wsum[wid] = inc;
    __syncthreads();
    if (wid == 0) {
        int w = wsum[lane], wi = w;
        #pragma unroll
        for (int off = 1; off < 32; off <<= 1) {
            int n = __shfl_up_sync(0xffffffffu, wi, off);
            if (lane >= off) wi += n;
        }
        wsum[lane] = wi - w;  // exclusive warp prefix
    }
    __syncthreads();
    int run = wsum[wid] + (inc - tsum);  // exclusive base for this thread's run
    #pragma unroll
    for (int j = 0; j < BINS_PER_THREAD; j++) {
        hist[base_bin + j] = run;  // becomes the scatter cursor
        run += v[j];
    }
    __syncthreads();

    // Phase C: scatter (ids re-read; hot in L1/L2 from Phase A).
    for (int i = tid; i < B; i += 1024) {
        const int pos = atomicAdd(&hist[time_id[i] * bpt + (item_id[i] >> 5)], 1);
        g_perm[pos] = i;
    }
}

// ---- main kernel ---------------------------------------------------------

__global__ void __launch_bounds__(256) ucf_kernel(
    const float* __restrict__ qos,      // [T,U,I]
    const float* __restrict__ user_avg, // [T,U]
    const float* __restrict__ sim,      // [U,U]
    const int*   __restrict__ user_id,
    const int*   __restrict__ item_id,
    const int*   __restrict__ time_id,
    float*       __restrict__ out,
    int B, int U, int I, int use_perm)
{
    const int warp = blockIdx.x * (blockDim.x >> 5) + (threadIdx.x >> 5);
    if (warp >= B) return;
    const int lane = threadIdx.x & 31;
    const int b = use_perm ? __ldg(&g_perm[warp]) : warp;

    const int u  = user_id[b];
    const int it = item_id[b];
    const int t  = time_id[b];

    const float* __restrict__ qcol = qos + ((size_t)t * U) * I + it;

    // Phase 1: 5 independent scattered gathers first. Sorted order makes
    // exact (t, i-line) sharers warp-adjacent -> L1/L2 hits.
    float q[JMAX];
    #pragma unroll
    for (int j = 0; j < JMAX; j++) {
        const int v = j * 32 + lane;
        q[j] = (v < U) ? __ldg(qcol + (size_t)v * I) : 0.0f;
    }

    // Phase 2: L2-resident rows.
    const float avg_u = __ldg(user_avg + (size_t)t * U + u);
    const float* __restrict__ simrow = sim + (size_t)u * U;
    const float* __restrict__ avgrow = user_avg + (size_t)t * U;

    unsigned o[JMAX];  // ordered masked-sim keys; 0 = removed / pad
    float    dv[JMAX]; // r_vs - avg_v

    #pragma unroll
    for (int j = 0; j < JMAX; j++) {
        const int v = j * 32 + lane;
        const bool ok = v < U;
        float s = ok ? __ldg(simrow + v) : 0.0f;
        float a = ok ? __ldg(avgrow + v) : 0.0f;
        dv[j] = q[j] - a;
        // Reference: sim_m = rated ? sim : 0.0 (zeros stay candidates);
        // only v>=U padding is excluded.
        o[j] = ok ? f2ord((q[j] > 0.0f) ? s : 0.0f) : 0u;
    }

    unsigned lb = 0u; int lj = 0;
    #pragma unroll
    for (int j = 0; j < JMAX; j++)
        if (o[j] > lb) { lb = o[j]; lj = j; }

    float contrib = 0.0f;
    float simsum  = 0.0f;

    // Phase 3: iterative top-10 extraction (redux max + ballot election).
    #pragma unroll
    for (int k = 0; k < 10; k++) {
        const unsigned m   = __reduce_max_sync(0xffffffffu, lb);
        const unsigned bal = __ballot_sync(0xffffffffu, lb == m);
        const int      wl  = __ffs(bal) - 1;  // ties are zero-weight-safe
        simsum += ord2f(m);
        if (lane == wl) {
            const float w = ord2f(m);
            #pragma unroll
            for (int j = 0; j < JMAX; j++)
                if (j == lj) { contrib += w * dv[j]; o[j] = 0u; }
            lb = 0u; lj = 0;
            #pragma unroll
            for (int j = 0; j < JMAX; j++)
                if (o[j] > lb) { lb = o[j]; lj = j; }
        }
    }

    #pragma unroll
    for (int off = 16; off; off >>= 1)
        contrib += __shfl_xor_sync(0xffffffffu, contrib, off);

    if (lane == 0) {
        float p = contrib / (simsum + 1e-8f);
        if (!isfinite(p)) p = 0.0f;  // mirrors jnp.nan_to_num
        out[b] = avg_u + p;
    }
}

extern "C" void kernel_launch(void* const* d_in, const int* in_sizes, int n_in,
                              void* d_out, int out_size)
{
    const float* qos      = (const float*)d_in[0];
    const float* user_avg = (const float*)d_in[1];
    const float* sim      = (const float*)d_in[2];
    const int*   user_id  = (const int*)d_in[3];
    const int*   item_id  = (const int*)d_in[4];
    const int*   time_id  = (const int*)d_in[5];
    float* out = (float*)d_out;

    int U = (int)(sqrt((double)in_sizes[2]) + 0.5);
    int T = in_sizes[1] / U;
    int I = in_sizes[0] / (T * U);
    int B = in_sizes[3];

    const int bpt = (I + 31) >> 5;  // bins per time slice
    const int use_perm = (T * bpt <= NBINS_PAD && B <= PERM_CAP) ? 1 : 0;
    if (use_perm)
        k_sort<<<1, 1024>>>(time_id, item_id, B, bpt);

    const int threads = 256;  // 8 warps/block, 1 element per warp
    const int wpb = threads / 32;
    const int blocks = (B + wpb - 1) / wpb;
    ucf_kernel<<<blocks, threads>>>(qos, user_avg, sim,
                                    user_id, item_id, time_id,
                                    out, B, U, I, use_perm);
}

// round 12
// speedup vs baseline: 1.5354x; 1.5354x over previous
#include <cuda_runtime.h>
#include <math.h>

// UserCollaborativeFiltering — round 12.
// Algorithmic cut: the reference's masked top-k (unrated -> 0.0, ~42 zeros
// always present) can never select a negative sim, and selected zeros
// contribute nothing. The exact answer depends only on the <=10 largest
// RATED positive-sim users. So: extract top-20 positive-sim candidates from
// the (L2-resident) sim row, probe just those 20 qos values in one batched
// scattered load, accept rated ones in rank order; rare extra batches if
// <10 accepted; exact full-gather fallback (R5 algorithm) if positives are
// exhausted (P ~ 1e-20, correctness-only path).
// Gather traffic: 175MB -> ~42MB, and the probed set is replay-invariant
// and L2-resident, so steady-state DRAM ~0.

#define JMAX 5  // ceil(142/32); requires U <= 160

// Monotone float -> u32 (order-preserving). 0u reserved as "removed";
// f2ord(x) for x>0 is >= 0x80000001 > 0.
__device__ __forceinline__ unsigned f2ord(float f) {
    unsigned b = __float_as_uint(f);
    return (b & 0x80000000u) ? ~b : (b | 0x80000000u);
}
__device__ __forceinline__ float ord2f(unsigned o) {
    unsigned b = (o & 0x80000000u) ? (o ^ 0x80000000u) : ~o;
    return __uint_as_float(b);
}

__global__ void __launch_bounds__(256) ucf_kernel(
    const float* __restrict__ qos,      // [T,U,I]
    const float* __restrict__ user_avg, // [T,U]
    const float* __restrict__ sim,      // [U,U]
    const int*   __restrict__ user_id,
    const int*   __restrict__ item_id,
    const int*   __restrict__ time_id,
    float*       __restrict__ out,
    int B, int U, int I)
{
    const unsigned FULL = 0xffffffffu;
    const int warp = blockIdx.x * (blockDim.x >> 5) + (threadIdx.x >> 5);
    if (warp >= B) return;
    const int lane = threadIdx.x & 31;

    const int u  = user_id[warp];
    const int it = item_id[warp];
    const int t  = time_id[warp];

    const float* __restrict__ qcol   = qos + ((size_t)t * U) * I + it;
    const float* __restrict__ simrow = sim + (size_t)u * U;
    const float* __restrict__ avgrow = user_avg + (size_t)t * U;
    const float avg_u = __ldg(avgrow + u);

    // Candidate keys: POSITIVE sims only (negatives/zeros can never be
    // selected with nonzero weight; see header proof). 0u = none/removed.
    unsigned o[JMAX];
    #pragma unroll
    for (int j = 0; j < JMAX; j++) {
        const int v = j * 32 + lane;
        float s = (v < U) ? __ldg(simrow + v) : 0.0f;
        o[j] = (s > 0.0f) ? f2ord(s) : 0u;
    }

    unsigned lb = 0u; int lj = 0;
    #pragma unroll
    for (int j = 0; j < JMAX; j++)
        if (o[j] > lb) { lb = o[j]; lj = j; }

    float cl = 0.0f;   // lane-local partial: sum w*(r - avg_v)
    float sl = 0.0f;   // lane-local partial: sum w
    int   acc = 0;     // accepted count (warp-uniform)
    bool  need_fallback = false;

    for (int batch = 0; batch < 8; batch++) {
        // ---- extract up to 20 candidates in descending sim order ----
        unsigned mk = 0u;  // this lane's captured candidate key (lane r = rank r)
        int      cv = 0;   // captured candidate user index
        int nc = 0;
        bool exhausted = false;
        #pragma unroll
        for (int r = 0; r < 20; r++) {
            const unsigned m = __reduce_max_sync(FULL, lb);
            if (!m) { exhausted = true; break; }       // warp-uniform
            const unsigned mycode = (unsigned)((lj << 5) | lane);  // == v
            const unsigned code = (lb == m) ? mycode : 0xffffffffu;
            const unsigned wc = __reduce_min_sync(FULL, code);  // lowest v
            if (lane == r) { mk = m; cv = (int)wc; }
            if (mycode == wc) {  // winner removes its entry, rescans
                o[lj] = 0u;
                lb = 0u; lj = 0;
                #pragma unroll
                for (int j = 0; j < JMAX; j++)
                    if (o[j] > lb) { lb = o[j]; lj = j; }
            }
            nc = r + 1;
        }

        // ---- one batched probe: qos[t, cv, i] on lanes 0..nc-1 ----
        const float qv = (lane < nc) ? __ldg(qcol + (size_t)cv * I) : 0.0f;
        const bool rated = (lane < nc) && (qv > 0.0f);
        const unsigned bal = __ballot_sync(FULL, rated);
        const int rankr = __popc(bal & ((1u << lane) - 1u));
        if (rated && (acc + rankr < 10)) {
            const float a = __ldg(avgrow + cv);
            const float w = ord2f(mk);
            cl += w * (qv - a);
            sl += w;
        }
        const int nr = __popc(bal);
        acc += (nr < 10 - acc) ? nr : (10 - acc);
        if (acc >= 10) break;
        if (exhausted) { need_fallback = true; break; }
    }

    if (need_fallback) {
        // Exact reference semantics for the (astronomically rare) case of
        // fewer than 10 rated positive-sim users: full-gather R5 algorithm
        // (zeros stay candidates; negatives can enter). Recompute from
        // scratch; overwrite partial sums.
        float dv[JMAX]; unsigned o2[JMAX];
        #pragma unroll
        for (int j = 0; j < JMAX; j++) {
            const int v = j * 32 + lane;
            const bool ok = v < U;
            float q = ok ? __ldg(qcol + (size_t)v * I) : 0.0f;
            float s = ok ? __ldg(simrow + v) : 0.0f;
            float a = ok ? __ldg(avgrow + v) : 0.0f;
            dv[j] = q - a;
            o2[j] = ok ? f2ord((q > 0.0f) ? s : 0.0f) : 0u;
        }
        unsigned lb2 = 0u; int lj2 = 0;
        #pragma unroll
        for (int j = 0; j < JMAX; j++)
            if (o2[j] > lb2) { lb2 = o2[j]; lj2 = j; }
        cl = 0.0f; sl = 0.0f;
        #pragma unroll
        for (int k = 0; k < 10; k++) {
            const unsigned m = __reduce_max_sync(FULL, lb2);
            const unsigned mycode = (unsigned)((lj2 << 5) | lane);
            const unsigned code = (lb2 == m) ? mycode : 0xffffffffu;
            const unsigned wc = __reduce_min_sync(FULL, code);
            if (lane == 0) sl += ord2f(m);  // uniform value; add on one lane
            if (mycode == wc) {
                cl += ord2f(m) * dv[lj2];
                o2[lj2] = 0u;
                lb2 = 0u; lj2 = 0;
                #pragma unroll
                for (int j = 0; j < JMAX; j++)
                    if (o2[j] > lb2) { lb2 = o2[j]; lj2 = j; }
            }
        }
    }

    // Cross-lane reduction of both partials.
    #pragma unroll
    for (int off = 16; off; off >>= 1) {
        cl += __shfl_xor_sync(FULL, cl, off);
        sl += __shfl_xor_sync(FULL, sl, off);
    }

    if (lane == 0) {
        float p = cl / (sl + 1e-8f);
        if (!isfinite(p)) p = 0.0f;  // mirrors jnp.nan_to_num
        out[warp] = avg_u + p;
    }
}

extern "C" void kernel_launch(void* const* d_in, const int* in_sizes, int n_in,
                              void* d_out, int out_size)
{
    const float* qos      = (const float*)d_in[0];
    const float* user_avg = (const float*)d_in[1];
    const float* sim      = (const float*)d_in[2];
    const int*   user_id  = (const int*)d_in[3];
    const int*   item_id  = (const int*)d_in[4];
    const int*   time_id  = (const int*)d_in[5];
    float* out = (float*)d_out;

    int U = (int)(sqrt((double)in_sizes[2]) + 0.5);
    int T = in_sizes[1] / U;
    int I = in_sizes[0] / (T * U);
    int B = in_sizes[3];

    const int threads = 256;  // 8 warps/block, 1 element per warp
    const int wpb = threads / 32;
    const int blocks = (B + wpb - 1) / wpb;
    ucf_kernel<<<blocks, threads>>>(qos, user_avg, sim,
                                    user_id, item_id, time_id,
                                    out, B, U, I);
}

// round 13
// speedup vs baseline: 2.2565x; 1.4697x over previous
#include <cuda_runtime.h>
#include <math.h>

// UserCollaborativeFiltering — round 13.
// R12 made the problem compute-bound (DRAM 17%, issue 65%): the 20 ordered
// redux_max/redux_min extraction rounds were the wall. This round selects
// the candidate SET by threshold (warp bisection, ~6 reduce_add steps),
// compacts one-candidate-per-lane via ballot prefix + smem, probes once,
// and only orders the rated survivors (10 cheap single-register redux
// rounds). Rare <10-rated case handled exactly by the tranche loop:
// all rated candidates above a threshold are globally top-ranked, and if
// positives are exhausted, accumulating every rated positive IS the exact
// reference answer (zeros fill the remaining top-k slots with zero weight).

#define JMAX 5  // ceil(142/32); requires U <= 160
#define FULL 0xffffffffu

// Monotone float -> u32 (order-preserving); x>0 maps to >= 0x80000001.
__device__ __forceinline__ unsigned f2ord(float f) {
    unsigned b = __float_as_uint(f);
    return (b & 0x80000000u) ? ~b : (b | 0x80000000u);
}
__device__ __forceinline__ float ord2f(unsigned o) {
    unsigned b = (o & 0x80000000u) ? (o ^ 0x80000000u) : ~o;
    return __uint_as_float(b);
}

__global__ void __launch_bounds__(256) ucf_kernel(
    const float* __restrict__ qos,      // [T,U,I]
    const float* __restrict__ user_avg, // [T,U]
    const float* __restrict__ sim,      // [U,U]
    const int*   __restrict__ user_id,
    const int*   __restrict__ item_id,
    const int*   __restrict__ time_id,
    float*       __restrict__ out,
    int B, int U, int I)
{
    __shared__ unsigned skey[8][32];
    __shared__ int      sidx[8][32];

    const int warp = blockIdx.x * (blockDim.x >> 5) + (threadIdx.x >> 5);
    if (warp >= B) return;
    const int lane = threadIdx.x & 31;
    const int w8   = threadIdx.x >> 5;

    const int u  = user_id[warp];
    const int it = item_id[warp];
    const int t  = time_id[warp];

    const float* __restrict__ qcol   = qos + ((size_t)t * U) * I + it;
    const float* __restrict__ simrow = sim + (size_t)u * U;
    const float* __restrict__ avgrow = user_avg + (size_t)t * U;
    const float avg_u = __ldg(avgrow + u);

    // Positive-sim candidate keys (negatives/zeros can never carry weight:
    // the ~42 unrated zeros always outrank negatives, and zeros weigh 0).
    unsigned o[JMAX];
    int lcnt = 0;
    #pragma unroll
    for (int j = 0; j < JMAX; j++) {
        const int v = j * 32 + lane;
        float s = (v < U) ? __ldg(simrow + v) : 0.0f;
        o[j] = (s > 0.0f) ? f2ord(s) : 0u;
        lcnt += (o[j] != 0u);
    }
    int total = __reduce_add_sync(FULL, lcnt);  // remaining positive keys

    float cl = 0.0f, sl = 0.0f;  // lane-local partials: sum w*(q-a), sum w
    int acc = 0;

    while (acc < 10 && total > 0) {
        // ---- threshold: 16..32 keys above it (exact bisection on u32) ----
        unsigned thresh = 1u;  // if total<=32, take everything
        if (total > 32) {
            unsigned lo = 1u, hi = 0xffffffffu;  // cnt(lo)>32, cnt(hi)<=32
            while (hi - lo > 1u) {
                const unsigned m = lo + ((hi - lo) >> 1);
                int c = 0;
                #pragma unroll
                for (int j = 0; j < JMAX; j++) c += (o[j] >= m);
                c = __reduce_add_sync(FULL, c);
                if (c > 32) lo = m;
                else { hi = m; if (c >= 16) break; }
            }
            thresh = hi;  // distinct keys => cnt(hi) in [1,32]
        }

        // ---- compact selected candidates: one per lane via smem ----
        int cnt = 0;
        #pragma unroll
        for (int j = 0; j < JMAX; j++) {
            const bool sel = (o[j] >= thresh);
            const unsigned bal = __ballot_sync(FULL, sel);
            const int pos = cnt + __popc(bal & ((1u << lane) - 1u));
            if (sel && pos < 32) {
                skey[w8][pos] = o[j];
                sidx[w8][pos] = j * 32 + lane;
                o[j] = 0u;  // consumed this tranche (all branches below)
            }
            cnt += __popc(bal);
        }
        cnt = (cnt < 32) ? cnt : 32;
        total -= cnt;
        __syncwarp();
        unsigned mykey = 0u; int myv = 0;
        if (lane < cnt) { mykey = skey[w8][lane]; myv = sidx[w8][lane]; }
        __syncwarp();

        // ---- single batched probe of this tranche ----
        const float q = (lane < cnt) ? __ldg(qcol + (size_t)myv * I) : 0.0f;
        const bool rated = (lane < cnt) && (q > 0.0f);
        const int R = __popc(__ballot_sync(FULL, rated));

        if (acc + R <= 10) {
            // every rated candidate here is in the global top-10 rated
            if (rated) {
                const float a = __ldg(avgrow + myv);
                const float w = ord2f(mykey);
                cl += w * (q - a);
                sl += w;
            }
            acc += R;
        } else {
            // take exactly the (10-acc) largest rated of this tranche
            const int need = 10 - acc;
            unsigned kk = rated ? mykey : 0u;
            for (int r = 0; r < need; r++) {
                const unsigned m  = __reduce_max_sync(FULL, kk);
                const unsigned bl = __ballot_sync(FULL, kk == m && m != 0u);
                const int wl = __ffs(bl) - 1;
                if (lane == wl) {
                    const float a = __ldg(avgrow + myv);
                    const float w = ord2f(m);
                    cl += w * (q - a);
                    sl += w;
                    kk = 0u;
                }
            }
            acc = 10;
        }
    }
    // Loop exit with acc<10 means all rated positive users are accumulated:
    // exact (remaining top-k slots are zeros with zero weight).

    #pragma unroll
    for (int off = 16; off; off >>= 1) {
        cl += __shfl_xor_sync(FULL, cl, off);
        sl += __shfl_xor_sync(FULL, sl, off);
    }

    if (lane == 0) {
        float p = cl / (sl + 1e-8f);
        if (!isfinite(p)) p = 0.0f;  // mirrors jnp.nan_to_num
        out[warp] = avg_u + p;
    }
}

extern "C" void kernel_launch(void* const* d_in, const int* in_sizes, int n_in,
                              void* d_out, int out_size)
{
    const float* qos      = (const float*)d_in[0];
    const float* user_avg = (const float*)d_in[1];
    const float* sim      = (const float*)d_in[2];
    const int*   user_id  = (const int*)d_in[3];
    const int*   item_id  = (const int*)d_in[4];
    const int*   time_id  = (const int*)d_in[5];
    float* out = (float*)d_out;

    int U = (int)(sqrt((double)in_sizes[2]) + 0.5);
    int T = in_sizes[1] / U;
    int I = in_sizes[0] / (T * U);
    int B = in_sizes[3];

    const int threads = 256;  // 8 warps/block, 1 element per warp
    const int wpb = threads / 32;
    const int blocks = (B + wpb - 1) / wpb;
    ucf_kernel<<<blocks, threads>>>(qos, user_avg, sim,
                                    user_id, item_id, time_id,
                                    out, B, U, I);
}

// round 14
// speedup vs baseline: 2.4706x; 1.0949x over previous
#include <cuda_runtime.h>
#include <math.h>

// UserCollaborativeFiltering — round 14.
// R13 analysis: ~820 issued warp-instrs/sample, dominated by the threshold
// bisection starting on the full u32 space (exp ~12 iters, tail to ~31).
// Fixes: (1) seed bisection bounds with warp min/max of the live keys
// (~2^26 interval instead of 2^32), (2) widen accept window to [12,32],
// (3) cap iterations at 16 — the c(hi)<=32 invariant makes cap-out safe
// (smaller tranche, never incorrect). Selection/probe/accept logic is
// unchanged from the passing R13 kernel.

#define JMAX 5  // ceil(142/32); requires U <= 160
#define FULL 0xffffffffu

// Monotone float -> u32 (order-preserving); x>0 maps to >= 0x80000001.
__device__ __forceinline__ unsigned f2ord(float f) {
    unsigned b = __float_as_uint(f);
    return (b & 0x80000000u) ? ~b : (b | 0x80000000u);
}
__device__ __forceinline__ float ord2f(unsigned o) {
    unsigned b = (o & 0x80000000u) ? (o ^ 0x80000000u) : ~o;
    return __uint_as_float(b);
}

__global__ void __launch_bounds__(256) ucf_kernel(
    const float* __restrict__ qos,      // [T,U,I]
    const float* __restrict__ user_avg, // [T,U]
    const float* __restrict__ sim,      // [U,U]
    const int*   __restrict__ user_id,
    const int*   __restrict__ item_id,
    const int*   __restrict__ time_id,
    float*       __restrict__ out,
    int B, int U, int I)
{
    __shared__ unsigned skey[8][32];
    __shared__ int      sidx[8][32];

    const int warp = blockIdx.x * (blockDim.x >> 5) + (threadIdx.x >> 5);
    if (warp >= B) return;
    const int lane = threadIdx.x & 31;
    const int w8   = threadIdx.x >> 5;

    const int u  = user_id[warp];
    const int it = item_id[warp];
    const int t  = time_id[warp];

    const float* __restrict__ qcol   = qos + ((size_t)t * U) * I + it;
    const float* __restrict__ simrow = sim + (size_t)u * U;
    const float* __restrict__ avgrow = user_avg + (size_t)t * U;
    const float avg_u = __ldg(avgrow + u);

    // Positive-sim candidate keys (negatives/zeros can never carry weight:
    // ~42 unrated zeros always outrank negatives, and zeros weigh 0).
    unsigned o[JMAX];
    int lcnt = 0;
    #pragma unroll
    for (int j = 0; j < JMAX; j++) {
        const int v = j * 32 + lane;
        float s = (v < U) ? __ldg(simrow + v) : 0.0f;
        o[j] = (s > 0.0f) ? f2ord(s) : 0u;
        lcnt += (o[j] != 0u);
    }
    int total = __reduce_add_sync(FULL, lcnt);

    float cl = 0.0f, sl = 0.0f;  // lane partials: sum w*(q-a), sum w
    int acc = 0;

    while (acc < 10 && total > 0) {
        // ---- threshold via seeded, capped bisection: count in [1,32] ----
        unsigned thresh = 1u;  // total<=32: take everything
        if (total > 32) {
            // Seed bounds from the live keys (2 redux ops).
            unsigned lmax = 0u, lmin = FULL;
            #pragma unroll
            for (int j = 0; j < JMAX; j++) {
                const unsigned k = o[j];
                if (k > lmax) lmax = k;
                if (k && k < lmin) lmin = k;
            }
            unsigned lo = __reduce_min_sync(FULL, lmin);      // c(lo)=total>32
            unsigned hi = __reduce_max_sync(FULL, lmax) + 1u; // c(hi)=0<=32
            for (int itr = 0; itr < 16 && hi - lo > 1u; itr++) {
                const unsigned m = lo + ((hi - lo) >> 1);
                int c = 0;
                #pragma unroll
                for (int j = 0; j < JMAX; j++) c += (o[j] >= m);
                c = __reduce_add_sync(FULL, c);
                if (c > 32) lo = m;
                else { hi = m; if (c >= 12) break; }
            }
            thresh = hi;  // invariant: c(hi) <= 32 (may be small on cap-out)
        }

        // ---- compact selected candidates: one per lane via smem ----
        int cnt = 0;
        #pragma unroll
        for (int j = 0; j < JMAX; j++) {
            const bool sel = (o[j] >= thresh);
            const unsigned bal = __ballot_sync(FULL, sel);
            const int pos = cnt + __popc(bal & ((1u << lane) - 1u));
            if (sel && pos < 32) {
                skey[w8][pos] = o[j];
                sidx[w8][pos] = j * 32 + lane;
                o[j] = 0u;  // consumed this tranche
            }
            cnt += __popc(bal);
        }
        cnt = (cnt < 32) ? cnt : 32;   // c<=32 guaranteed; clamp for safety
        total -= cnt;
        __syncwarp();
        unsigned mykey = 0u; int myv = 0;
        if (lane < cnt) { mykey = skey[w8][lane]; myv = sidx[w8][lane]; }
        __syncwarp();

        // ---- single batched probe of this tranche ----
        const float q = (lane < cnt) ? __ldg(qcol + (size_t)myv * I) : 0.0f;
        const bool rated = (lane < cnt) && (q > 0.0f);
        const int R = __popc(__ballot_sync(FULL, rated));

        if (acc + R <= 10) {
            // every rated candidate here is in the global top-10 rated
            if (rated) {
                const float a = __ldg(avgrow + myv);
                const float w = ord2f(mykey);
                cl += w * (q - a);
                sl += w;
            }
            acc += R;
        } else {
            // take exactly the (10-acc) largest rated of this tranche
            const int need = 10 - acc;
            unsigned kk = rated ? mykey : 0u;
            for (int r = 0; r < need; r++) {
                const unsigned m  = __reduce_max_sync(FULL, kk);
                const unsigned bl = __ballot_sync(FULL, kk == m && m != 0u);
                const int wl = __ffs(bl) - 1;
                if (lane == wl) {
                    const float a = __ldg(avgrow + myv);
                    const float w = ord2f(m);
                    cl += w * (q - a);
                    sl += w;
                    kk = 0u;
                }
            }
            acc = 10;
        }
    }
    // Exit with acc<10 == all rated positive users accumulated: exact
    // (remaining top-k slots are zeros with zero weight).

    #pragma unroll
    for (int off = 16; off; off >>= 1) {
        cl += __shfl_xor_sync(FULL, cl, off);
        sl += __shfl_xor_sync(FULL, sl, off);
    }

    if (lane == 0) {
        float p = cl / (sl + 1e-8f);
        if (!isfinite(p)) p = 0.0f;  // mirrors jnp.nan_to_num
        out[warp] = avg_u + p;
    }
}

extern "C" void kernel_launch(void* const* d_in, const int* in_sizes, int n_in,
                              void* d_out, int out_size)
{
    const float* qos      = (const float*)d_in[0];
    const float* user_avg = (const float*)d_in[1];
    const float* sim      = (const float*)d_in[2];
    const int*   user_id  = (const int*)d_in[3];
    const int*   item_id  = (const int*)d_in[4];
    const int*   time_id  = (const int*)d_in[5];
    float* out = (float*)d_out;

    int U = (int)(sqrt((double)in_sizes[2]) + 0.5);
    int T = in_sizes[1] / U;
    int I = in_sizes[0] / (T * U);
    int B = in_sizes[3];

    const int threads = 256;  // 8 warps/block, 1 element per warp
    const int wpb = threads / 32;
    const int blocks = (B + wpb - 1) / wpb;
    ucf_kernel<<<blocks, threads>>>(qos, user_avg, sim,
                                    user_id, item_id, time_id,
                                    out, B, U, I);
}